// round 7
// baseline (speedup 1.0000x reference)
#include <cuda_runtime.h>
#include <cuda_bf16.h>
#include <cstdint>
#include <cstddef>

// ---------------------------------------------------------------------------
// pre[b,o,d] = sum_{h,f} W[o, h*64+f] * x[b,h,d] * inp[b,f,d] + bias[o]
// x_next = relu(pre);  out[:, off+o] = sum_d relu(pre);  3 chained layers.
// B=512, F=64, D=32, O=128.
//
// GEMM per layer: D[o=128, n=(b*32+d)] = W[o,k] * Z[k,n], Z built in SMEM.
// mma.sync m16n8k16 bf16, 3-MMA split (Whi*Zhi + Whi*Zlo + Wlo*Zhi).
// Round-7: 512 threads / 16 warps (4 per SMSP) -- warp tile m16 x n64 -- to
// cover produce/barrier bubbles that kept the tensor pipe at 60%.
// ---------------------------------------------------------------------------

#define SW128(o) ((o) ^ (((o) >> 3) & 0x70))

__device__ __align__(16) float g_x1[512 * 128 * 32];
__device__ __align__(16) float g_x2[512 * 128 * 32];
__device__ uint4 g_W0[128 * 4096 * 4 / 16];
__device__ uint4 g_W1[128 * 8192 * 4 / 16];
__device__ uint4 g_W2[128 * 8192 * 4 / 16];

__device__ __forceinline__ uint32_t smem_u32(const void* p) {
    uint32_t a;
    asm("{ .reg .u64 t; cvta.to.shared.u64 t, %1; cvt.u32.u64 %0, t; }"
        : "=r"(a) : "l"(p));
    return a;
}

__device__ __forceinline__ void split2(float z0, float z1,
                                       uint32_t& hi, uint32_t& lo) {
    __nv_bfloat162 h = __floats2bfloat162_rn(z0, z1);
    float2 hf = __bfloat1622float2(h);
    __nv_bfloat162 l = __floats2bfloat162_rn(z0 - hf.x, z1 - hf.y);
    hi = reinterpret_cast<uint32_t&>(h);
    lo = reinterpret_cast<uint32_t&>(l);
}

__device__ __forceinline__ void ldsm4(uint32_t r[4], uint32_t addr) {
    asm volatile("ldmatrix.sync.aligned.m8n8.x4.shared.b16 {%0,%1,%2,%3}, [%4];"
                 : "=r"(r[0]), "=r"(r[1]), "=r"(r[2]), "=r"(r[3]) : "r"(addr));
}

__device__ __forceinline__ void mma_bf16(float c[4], const uint32_t a[4],
                                         uint32_t b0, uint32_t b1) {
    asm volatile(
        "mma.sync.aligned.m16n8k16.row.col.f32.bf16.bf16.f32 "
        "{%0,%1,%2,%3}, {%4,%5,%6,%7}, {%8,%9}, {%0,%1,%2,%3};"
        : "+f"(c[0]), "+f"(c[1]), "+f"(c[2]), "+f"(c[3])
        : "r"(a[0]), "r"(a[1]), "r"(a[2]), "r"(a[3]), "r"(b0), "r"(b1));
}

// --------------------------- W prep: fp32 -> split bf16 tiles ---------------
__global__ __launch_bounds__(256)
void prep_w(const float* __restrict__ W, uint4* __restrict__ dst, int K) {
    int idx = blockIdx.x * 256 + threadIdx.x;
    int cpr = K >> 3;
    if (idx >= 128 * cpr) return;
    int o = idx / cpr;
    int k = (idx % cpr) * 8;
    const float4* src = (const float4*)(W + (size_t)o * K + k);
    float4 v0 = src[0], v1 = src[1];
    float zf[8] = {v0.x, v0.y, v0.z, v0.w, v1.x, v1.y, v1.z, v1.w};
    uint32_t hi[4], lo[4];
#pragma unroll
    for (int p = 0; p < 4; p++) split2(zf[2 * p], zf[2 * p + 1], hi[p], lo[p]);
    char* base = (char*)dst + (size_t)(k >> 6) * 32768;
    uint32_t off = SW128((uint32_t)(o * 128 + (k & 63) * 2));
    *(uint4*)(base + off)         = make_uint4(hi[0], hi[1], hi[2], hi[3]);
    *(uint4*)(base + 16384 + off) = make_uint4(lo[0], lo[1], lo[2], lo[3]);
}

// --------------------------- main layer kernel ------------------------------
// SMEM: [0,32768) inp_s; [32768 + s*65536): Whi(16K) Wlo(16K) Zhi(16K) Zlo(16K)
#define SMEM_TOTAL 163840
#define STAGE_OFF  32768

template <int H, bool WRITE_NEXT>
__global__ __launch_bounds__(512, 1)
void layer_mma(const float* __restrict__ x,
               const float* __restrict__ inp,
               const uint4* __restrict__ Wsp,
               const float* __restrict__ bias,
               float* __restrict__ x_next,
               float* __restrict__ out,
               int out_off)
{
    extern __shared__ char smem[];
    const uint32_t sb = smem_u32(smem);
    float* inp_s = (float*)smem;
    const int tid  = threadIdx.x;
    const int lane = tid & 31;
    const int w    = tid >> 5;
    const int wm   = w & 7;      // m16 block
    const int wn   = w >> 3;     // n64 block
    const int b0   = blockIdx.x * 4;

    {   // stage inp (8192 floats, 512 threads -> 4 x float4 each)
        const float4* src = (const float4*)(inp + (size_t)b0 * 2048);
        float4* dst = (float4*)inp_s;
#pragma unroll
        for (int i = 0; i < 4; i++) dst[tid + i * 512] = src[tid + i * 512];
    }

    // Producer constants: thread -> (n, k-quarter of 16)
    const int n  = tid & 127;
    const int bq = n >> 5;
    const int dd = n & 31;
    const int kq = tid >> 7;                       // 0..3
    const float* xp = x + ((size_t)(b0 + bq) * H) * 32 + dd;
    const float* ip = inp_s + (size_t)bq * 2048 + (kq * 16) * 32 + dd;
    const uint32_t zrow  = (uint32_t)n * 128;
    const uint32_t zmask = (uint32_t)((n & 7) << 4);
    const uint32_t zcol0 = (uint32_t)(kq * 32);    // bytes

    // MMA constants
    const int g = lane >> 3;
    const uint32_t maskL = (uint32_t)((lane & 7) << 4);
    uint32_t aRowB, bRow[4], aCol[4], bCol[4];
    aRowB = (uint32_t)((16 * wm + (lane & 7) + (g & 1) * 8) * 128);
#pragma unroll
    for (int p = 0; p < 4; p++)
        bRow[p] = (uint32_t)((64 * wn + 16 * p + 8 * ((g >> 1) & 1) + (lane & 7)) * 128);
#pragma unroll
    for (int kk = 0; kk < 4; kk++) {
        aCol[kk] = ((uint32_t)(((g >> 1) & 1) * 16 + 32 * kk)) ^ maskL;
        bCol[kk] = ((uint32_t)((g & 1) * 16 + 32 * kk)) ^ maskL;
    }

    float C[8][4];
#pragma unroll
    for (int j = 0; j < 8; j++)
#pragma unroll
        for (int q = 0; q < 4; q++) C[j][q] = 0.f;

    const char* gW = (const char*)Wsp;

    auto prodZ = [&](int h, int s) {
        char* zp = smem + STAGE_OFF + s * 65536 + 32768;
        const float xv = __ldg(xp + h * 32);
#pragma unroll
        for (int i = 0; i < 2; i++) {
            float z[8];
#pragma unroll
            for (int j = 0; j < 8; j++) z[j] = xv * ip[(i * 8 + j) * 32];
            uint32_t hi[4], lo[4];
#pragma unroll
            for (int p = 0; p < 4; p++)
                split2(z[2 * p], z[2 * p + 1], hi[p], lo[p]);
            uint32_t off = zrow + ((zcol0 + 16u * i) ^ zmask);
            *(uint4*)(zp + off)         = make_uint4(hi[0], hi[1], hi[2], hi[3]);
            *(uint4*)(zp + 16384 + off) = make_uint4(lo[0], lo[1], lo[2], lo[3]);
        }
    };
    auto copyW = [&](int it, int s) {
        uint32_t dsb = sb + STAGE_OFF + s * 65536 + tid * 16;
        const char* srcW = gW + (size_t)it * 32768 + tid * 16;
#pragma unroll
        for (int i = 0; i < 4; i++)
            asm volatile("cp.async.cg.shared.global [%0], [%1], 16;"
                         :: "r"(dsb + i * 8192), "l"(srcW + i * 8192));
        asm volatile("cp.async.commit_group;");
    };

    auto doMMA = [&](int s) {
        const uint32_t st = sb + STAGE_OFF + s * 65536;
#pragma unroll
        for (int kk = 0; kk < 4; kk++) {
            uint32_t ah[4], al[4], bh[4][4], bl[4][4];
            ldsm4(ah, st + aRowB + aCol[kk]);
            ldsm4(al, st + 16384 + aRowB + aCol[kk]);
#pragma unroll
            for (int p = 0; p < 4; p++) {
                ldsm4(bh[p], st + 32768 + bRow[p] + bCol[kk]);
                ldsm4(bl[p], st + 49152 + bRow[p] + bCol[kk]);
            }
#pragma unroll
            for (int p = 0; p < 4; p++)
#pragma unroll
                for (int q = 0; q < 2; q++)
                    mma_bf16(C[2 * p + q], ah, bh[p][2 * q], bh[p][2 * q + 1]);
#pragma unroll
            for (int p = 0; p < 4; p++)
#pragma unroll
                for (int q = 0; q < 2; q++)
                    mma_bf16(C[2 * p + q], ah, bl[p][2 * q], bl[p][2 * q + 1]);
#pragma unroll
            for (int p = 0; p < 4; p++)
#pragma unroll
                for (int q = 0; q < 2; q++)
                    mma_bf16(C[2 * p + q], al, bh[p][2 * q], bh[p][2 * q + 1]);
        }
    };

    __syncthreads();   // inp_s ready

    copyW(0, 0);
    prodZ(0, 0);

    // One barrier per tile; produce(s^1) overlaps MMA(s) (disjoint stages).
    // Per SMSP (w&3): warps with (w&4) MMA-first, others produce-first.
    for (int it = 0; it < H; ++it) {
        const int s = it & 1;
        __syncthreads();
        if (w & 4) {
            if (it + 1 < H) copyW(it + 1, s ^ 1);
            if (it + 1 < H) { asm volatile("cp.async.wait_group 1;"); }
            else            { asm volatile("cp.async.wait_group 0;"); }
            doMMA(s);
            if (it + 1 < H) prodZ(it + 1, s ^ 1);
        } else {
            if (it + 1 < H) { copyW(it + 1, s ^ 1); prodZ(it + 1, s ^ 1); }
            if (it + 1 < H) { asm volatile("cp.async.wait_group 1;"); }
            else            { asm volatile("cp.async.wait_group 0;"); }
            doMMA(s);
        }
    }

    // Epilogue: bias + relu, write x_next, reduce over d -> out
    const int mrow = lane >> 2;
    const int qn   = lane & 3;
#pragma unroll
    for (int h2 = 0; h2 < 2; h2++) {
        const int o = 16 * wm + 8 * h2 + mrow;
        const float bv = __ldg(bias + o);
#pragma unroll
        for (int bl2 = 0; bl2 < 2; bl2++) {
            const int b = b0 + 2 * wn + bl2;
            float sum = 0.f;
#pragma unroll
            for (int jj = 0; jj < 4; jj++) {
                const int j = 4 * bl2 + jj;
                float v0 = fmaxf(C[j][2 * h2]     + bv, 0.f);
                float v1 = fmaxf(C[j][2 * h2 + 1] + bv, 0.f);
                sum += v0 + v1;
                if (WRITE_NEXT) {
                    const int d = 8 * jj + 2 * qn;
                    *(float2*)(x_next + ((size_t)b * 128 + o) * 32 + d) =
                        make_float2(v0, v1);
                }
            }
            sum += __shfl_xor_sync(0xffffffffu, sum, 1);
            sum += __shfl_xor_sync(0xffffffffu, sum, 2);
            if (qn == 0) out[(size_t)b * 384 + out_off + o] = sum;
        }
    }
}

// ---------------------------------------------------------------------------
extern "C" void kernel_launch(void* const* d_in, const int* in_sizes, int n_in,
                              void* d_out, int out_size)
{
    (void)in_sizes; (void)n_in; (void)out_size;
    const float* input = (const float*)d_in[0];
    const float* W0    = (const float*)d_in[1];
    const float* b0    = (const float*)d_in[2];
    const float* W1    = (const float*)d_in[3];
    const float* b1    = (const float*)d_in[4];
    const float* W2    = (const float*)d_in[5];
    const float* b2    = (const float*)d_in[6];
    float* out = (float*)d_out;

    float *x1, *x2; uint4 *w0p, *w1p, *w2p;
    cudaGetSymbolAddress((void**)&x1, g_x1);
    cudaGetSymbolAddress((void**)&x2, g_x2);
    cudaGetSymbolAddress((void**)&w0p, g_W0);
    cudaGetSymbolAddress((void**)&w1p, g_W1);
    cudaGetSymbolAddress((void**)&w2p, g_W2);

    cudaFuncSetAttribute(layer_mma<64,  true >, cudaFuncAttributeMaxDynamicSharedMemorySize, SMEM_TOTAL);
    cudaFuncSetAttribute(layer_mma<128, true >, cudaFuncAttributeMaxDynamicSharedMemorySize, SMEM_TOTAL);
    cudaFuncSetAttribute(layer_mma<128, false>, cudaFuncAttributeMaxDynamicSharedMemorySize, SMEM_TOTAL);

    prep_w<<<256, 256>>>(W0, w0p, 4096);
    prep_w<<<512, 256>>>(W1, w1p, 8192);
    prep_w<<<512, 256>>>(W2, w2p, 8192);

    dim3 grid(128), block(512);
    layer_mma<64,  true ><<<grid, block, SMEM_TOTAL>>>(input, input, w0p, b0, x1, out, 0);
    layer_mma<128, true ><<<grid, block, SMEM_TOTAL>>>(x1,    input, w1p, b1, x2, out, 128);
    layer_mma<128, false><<<grid, block, SMEM_TOTAL>>>(x2,    input, w2p, b2, nullptr, out, 256);
}

// round 8
// speedup vs baseline: 1.1425x; 1.1425x over previous
#include <cuda_runtime.h>
#include <cuda_bf16.h>
#include <cstdint>
#include <cstddef>

// ---------------------------------------------------------------------------
// pre[b,o,d] = sum_{h,f} W[o, h*64+f] * x[b,h,d] * inp[b,f,d] + bias[o]
// x_next = relu(pre);  out[:, off+o] = sum_d relu(pre);  3 chained layers.
// B=512, F=64, D=32, O=128.
//
// GEMM per layer: D[o=128, n=(b*32+d)] = W[o,k] * Z[k,n], Z built in SMEM.
// mma.sync m16n8k16 bf16, 3-MMA split (Whi*Zhi + Whi*Zlo + Wlo*Zhi).
// Round-8: WARP SPECIALIZATION. Warps 0-7 = pure MMA consumers (m32 x n64),
// warps 8-15 = producers (W cp.async + Z gen). Full/empty mbarrier pairs per
// stage replace the per-tile __syncthreads that held tensor at 60%.
// ---------------------------------------------------------------------------

#define SW128(o) ((o) ^ (((o) >> 3) & 0x70))

__device__ __align__(16) float g_x1[512 * 128 * 32];
__device__ __align__(16) float g_x2[512 * 128 * 32];
__device__ uint4 g_W0[128 * 4096 * 4 / 16];
__device__ uint4 g_W1[128 * 8192 * 4 / 16];
__device__ uint4 g_W2[128 * 8192 * 4 / 16];

__device__ __forceinline__ uint32_t smem_u32(const void* p) {
    uint32_t a;
    asm("{ .reg .u64 t; cvta.to.shared.u64 t, %1; cvt.u32.u64 %0, t; }"
        : "=r"(a) : "l"(p));
    return a;
}

__device__ __forceinline__ void split2(float z0, float z1,
                                       uint32_t& hi, uint32_t& lo) {
    __nv_bfloat162 h = __floats2bfloat162_rn(z0, z1);
    float2 hf = __bfloat1622float2(h);
    __nv_bfloat162 l = __floats2bfloat162_rn(z0 - hf.x, z1 - hf.y);
    hi = reinterpret_cast<uint32_t&>(h);
    lo = reinterpret_cast<uint32_t&>(l);
}

__device__ __forceinline__ void ldsm4(uint32_t r[4], uint32_t addr) {
    asm volatile("ldmatrix.sync.aligned.m8n8.x4.shared.b16 {%0,%1,%2,%3}, [%4];"
                 : "=r"(r[0]), "=r"(r[1]), "=r"(r[2]), "=r"(r[3]) : "r"(addr));
}

__device__ __forceinline__ void mma_bf16(float c[4], const uint32_t a[4],
                                         uint32_t b0, uint32_t b1) {
    asm volatile(
        "mma.sync.aligned.m16n8k16.row.col.f32.bf16.bf16.f32 "
        "{%0,%1,%2,%3}, {%4,%5,%6,%7}, {%8,%9}, {%0,%1,%2,%3};"
        : "+f"(c[0]), "+f"(c[1]), "+f"(c[2]), "+f"(c[3])
        : "r"(a[0]), "r"(a[1]), "r"(a[2]), "r"(a[3]), "r"(b0), "r"(b1));
}

// --------------------------- mbarrier helpers -------------------------------
#define MBAR_INIT(a, c) \
    asm volatile("mbarrier.init.shared.b64 [%0], %1;" :: "r"(a), "r"(c) : "memory")
#define MBAR_ARRIVE(a) \
    asm volatile("mbarrier.arrive.release.cta.shared::cta.b64 _, [%0];" :: "r"(a) : "memory")
#define MBAR_WAIT(a, p) do { uint32_t _m = (a); uint32_t _p = (p); uint32_t _d;      \
    asm volatile("{\n\t.reg .pred q;\n\t"                                            \
        "mbarrier.try_wait.parity.acquire.cta.shared::cta.b64 q, [%1], %2;\n\t"      \
        "selp.b32 %0,1,0,q;\n\t}" : "=r"(_d) : "r"(_m), "r"(_p) : "memory");         \
    if (!_d) {                                                                       \
        asm volatile("{\n\t.reg .pred q;\n\t"                                        \
            "WL%=:\n\t"                                                              \
            "mbarrier.try_wait.parity.acquire.cta.shared::cta.b64 q, [%0], %1, 0x989680;\n\t" \
            "@q bra.uni WD%=;\n\t"                                                   \
            "bra.uni WL%=;\n\t"                                                      \
            "WD%=:\n\t}" :: "r"(_m), "r"(_p) : "memory");                            \
    } } while (0)

// --------------------------- W prep: fp32 -> split bf16 tiles ---------------
__global__ __launch_bounds__(256)
void prep_w(const float* __restrict__ W, uint4* __restrict__ dst, int K) {
    int idx = blockIdx.x * 256 + threadIdx.x;
    int cpr = K >> 3;
    if (idx >= 128 * cpr) return;
    int o = idx / cpr;
    int k = (idx % cpr) * 8;
    const float4* src = (const float4*)(W + (size_t)o * K + k);
    float4 v0 = src[0], v1 = src[1];
    float zf[8] = {v0.x, v0.y, v0.z, v0.w, v1.x, v1.y, v1.z, v1.w};
    uint32_t hi[4], lo[4];
#pragma unroll
    for (int p = 0; p < 4; p++) split2(zf[2 * p], zf[2 * p + 1], hi[p], lo[p]);
    char* base = (char*)dst + (size_t)(k >> 6) * 32768;
    uint32_t off = SW128((uint32_t)(o * 128 + (k & 63) * 2));
    *(uint4*)(base + off)         = make_uint4(hi[0], hi[1], hi[2], hi[3]);
    *(uint4*)(base + 16384 + off) = make_uint4(lo[0], lo[1], lo[2], lo[3]);
}

// --------------------------- main layer kernel ------------------------------
// SMEM: [0,32768) inp_s; [32768 + s*65536): Whi(16K) Wlo(16K) Zhi(16K) Zlo(16K)
//       [163840,163872): mbarriers full0 full1 empty0 empty1
#define STAGE_OFF  32768
#define MB_OFF     163840
#define SMEM_TOTAL 163968

template <int H, bool WRITE_NEXT>
__global__ __launch_bounds__(512, 1)
void layer_mma(const float* __restrict__ x,
               const float* __restrict__ inp,
               const uint4* __restrict__ Wsp,
               const float* __restrict__ bias,
               float* __restrict__ x_next,
               float* __restrict__ out,
               int out_off)
{
    extern __shared__ char smem[];
    const uint32_t sb = smem_u32(smem);
    float* inp_s = (float*)smem;
    const int tid  = threadIdx.x;
    const int lane = tid & 31;
    const int w    = tid >> 5;
    const int b0   = blockIdx.x * 4;

    const uint32_t FULL0  = sb + MB_OFF;
    const uint32_t FULL1  = sb + MB_OFF + 8;
    const uint32_t EMPTY0 = sb + MB_OFF + 16;
    const uint32_t EMPTY1 = sb + MB_OFF + 24;

    if (tid == 0) {
        MBAR_INIT(FULL0, 8);  MBAR_INIT(FULL1, 8);
        MBAR_INIT(EMPTY0, 8); MBAR_INIT(EMPTY1, 8);
    }

    {   // stage inp (8192 floats, 512 threads -> 4 x float4 each)
        const float4* src = (const float4*)(inp + (size_t)b0 * 2048);
        float4* dst = (float4*)inp_s;
#pragma unroll
        for (int i = 0; i < 4; i++) dst[tid + i * 512] = src[tid + i * 512];
    }
    __syncthreads();   // inp_s + mbarriers ready

    if (w >= 8) {
        // ==================== PRODUCERS (warps 8-15) ====================
        const int ptid = tid - 256;                // 0..255
        const int n  = ptid & 127;
        const int bq = n >> 5;
        const int dd = n & 31;
        const int kh = (ptid >> 7) * 32;
        const float* xp = x + ((size_t)(b0 + bq) * H) * 32 + dd;
        const float* ip = inp_s + (size_t)bq * 2048 + kh * 32 + dd;
        const uint32_t zrow  = (uint32_t)n * 128;
        const uint32_t zmask = (uint32_t)((n & 7) << 4);
        const uint32_t zcol0 = (uint32_t)(kh * 2);
        const char* gW = (const char*)Wsp;

        for (int it = 0; it < H; ++it) {
            const int s = it & 1;
            const uint32_t EMPTY = s ? EMPTY1 : EMPTY0;
            const uint32_t FULL  = s ? FULL1  : FULL0;
            if (it >= 2) MBAR_WAIT(EMPTY, (uint32_t)(((it >> 1) - 1) & 1));

            // W tile via cp.async (layout matches SMEM 1:1)
            {
                uint32_t dsb = sb + STAGE_OFF + s * 65536 + ptid * 16;
                const char* srcW = gW + (size_t)it * 32768 + ptid * 16;
#pragma unroll
                for (int i = 0; i < 8; i++)
                    asm volatile("cp.async.cg.shared.global [%0], [%1], 16;"
                                 :: "r"(dsb + i * 4096), "l"(srcW + i * 4096));
                asm volatile("cp.async.commit_group;");
            }
            // Z tile: z[n][k] = x[b,h,d] * inp[b, k, d], split hi/lo
            {
                char* zp = smem + STAGE_OFF + s * 65536 + 32768;
                const float xv = __ldg(xp + it * 32);
#pragma unroll
                for (int i = 0; i < 4; i++) {
                    float z[8];
#pragma unroll
                    for (int j = 0; j < 8; j++) z[j] = xv * ip[(i * 8 + j) * 32];
                    uint32_t hi[4], lo[4];
#pragma unroll
                    for (int p = 0; p < 4; p++)
                        split2(z[2 * p], z[2 * p + 1], hi[p], lo[p]);
                    uint32_t off = zrow + ((zcol0 + 16u * i) ^ zmask);
                    *(uint4*)(zp + off)         = make_uint4(hi[0], hi[1], hi[2], hi[3]);
                    *(uint4*)(zp + 16384 + off) = make_uint4(lo[0], lo[1], lo[2], lo[3]);
                }
            }
            asm volatile("cp.async.wait_group 0;");
            __syncwarp();
            if (lane == 0) MBAR_ARRIVE(FULL);
        }
        // producers exit (no epilogue state)
        return;
    }

    // ==================== CONSUMERS (warps 0-7) ====================
    const int wm = w & 3;     // m32 block
    const int wn = w >> 2;    // n64 block

    const int g = lane >> 3;
    const uint32_t maskL = (uint32_t)((lane & 7) << 4);
    uint32_t aRow[2], bRow[4], aCol[4], bCol[4];
#pragma unroll
    for (int mi = 0; mi < 2; mi++)
        aRow[mi] = (uint32_t)((32 * wm + 16 * mi + (lane & 7) + (g & 1) * 8) * 128);
#pragma unroll
    for (int p = 0; p < 4; p++)
        bRow[p] = (uint32_t)((64 * wn + 16 * p + 8 * ((g >> 1) & 1) + (lane & 7)) * 128);
#pragma unroll
    for (int kk = 0; kk < 4; kk++) {
        aCol[kk] = ((uint32_t)(((g >> 1) & 1) * 16 + 32 * kk)) ^ maskL;
        bCol[kk] = ((uint32_t)((g & 1) * 16 + 32 * kk)) ^ maskL;
    }

    float C[2][8][4];
#pragma unroll
    for (int i = 0; i < 2; i++)
#pragma unroll
        for (int j = 0; j < 8; j++)
#pragma unroll
            for (int q = 0; q < 4; q++) C[i][j][q] = 0.f;

    for (int it = 0; it < H; ++it) {
        const int s = it & 1;
        const uint32_t FULL  = s ? FULL1  : FULL0;
        const uint32_t EMPTY = s ? EMPTY1 : EMPTY0;
        MBAR_WAIT(FULL, (uint32_t)((it >> 1) & 1));

        const uint32_t st = sb + STAGE_OFF + s * 65536;
#pragma unroll
        for (int kk = 0; kk < 4; kk++) {
            uint32_t ah[2][4], al[2][4];
#pragma unroll
            for (int mi = 0; mi < 2; mi++) {
                ldsm4(ah[mi], st + aRow[mi] + aCol[kk]);
                ldsm4(al[mi], st + 16384 + aRow[mi] + aCol[kk]);
            }
#pragma unroll
            for (int p = 0; p < 4; p++) {
                uint32_t bh[4], bl[4];
                ldsm4(bh, st + 32768 + bRow[p] + bCol[kk]);
                ldsm4(bl, st + 49152 + bRow[p] + bCol[kk]);
#pragma unroll
                for (int mi = 0; mi < 2; mi++) {
#pragma unroll
                    for (int q = 0; q < 2; q++) {
                        float* c = C[mi][2 * p + q];
                        mma_bf16(c, ah[mi], bh[2 * q], bh[2 * q + 1]);
                        mma_bf16(c, ah[mi], bl[2 * q], bl[2 * q + 1]);
                        mma_bf16(c, al[mi], bh[2 * q], bh[2 * q + 1]);
                    }
                }
            }
        }
        __syncwarp();
        if (lane == 0) MBAR_ARRIVE(EMPTY);
    }

    // Epilogue: bias + relu, write x_next, reduce over d -> out
    const int mrow = lane >> 2;
    const int qn   = lane & 3;
#pragma unroll
    for (int mi = 0; mi < 2; mi++) {
#pragma unroll
        for (int h2 = 0; h2 < 2; h2++) {
            const int o = 32 * wm + 16 * mi + 8 * h2 + mrow;
            const float bv = __ldg(bias + o);
#pragma unroll
            for (int bl2 = 0; bl2 < 2; bl2++) {
                const int b = b0 + 2 * wn + bl2;
                float sum = 0.f;
#pragma unroll
                for (int jj = 0; jj < 4; jj++) {
                    const int j = 4 * bl2 + jj;
                    float v0 = fmaxf(C[mi][j][2 * h2]     + bv, 0.f);
                    float v1 = fmaxf(C[mi][j][2 * h2 + 1] + bv, 0.f);
                    sum += v0 + v1;
                    if (WRITE_NEXT) {
                        const int d = 8 * jj + 2 * qn;
                        *(float2*)(x_next + ((size_t)b * 128 + o) * 32 + d) =
                            make_float2(v0, v1);
                    }
                }
                sum += __shfl_xor_sync(0xffffffffu, sum, 1);
                sum += __shfl_xor_sync(0xffffffffu, sum, 2);
                if (qn == 0) out[(size_t)b * 384 + out_off + o] = sum;
            }
        }
    }
}

// ---------------------------------------------------------------------------
extern "C" void kernel_launch(void* const* d_in, const int* in_sizes, int n_in,
                              void* d_out, int out_size)
{
    (void)in_sizes; (void)n_in; (void)out_size;
    const float* input = (const float*)d_in[0];
    const float* W0    = (const float*)d_in[1];
    const float* b0    = (const float*)d_in[2];
    const float* W1    = (const float*)d_in[3];
    const float* b1    = (const float*)d_in[4];
    const float* W2    = (const float*)d_in[5];
    const float* b2    = (const float*)d_in[6];
    float* out = (float*)d_out;

    float *x1, *x2; uint4 *w0p, *w1p, *w2p;
    cudaGetSymbolAddress((void**)&x1, g_x1);
    cudaGetSymbolAddress((void**)&x2, g_x2);
    cudaGetSymbolAddress((void**)&w0p, g_W0);
    cudaGetSymbolAddress((void**)&w1p, g_W1);
    cudaGetSymbolAddress((void**)&w2p, g_W2);

    cudaFuncSetAttribute(layer_mma<64,  true >, cudaFuncAttributeMaxDynamicSharedMemorySize, SMEM_TOTAL);
    cudaFuncSetAttribute(layer_mma<128, true >, cudaFuncAttributeMaxDynamicSharedMemorySize, SMEM_TOTAL);
    cudaFuncSetAttribute(layer_mma<128, false>, cudaFuncAttributeMaxDynamicSharedMemorySize, SMEM_TOTAL);

    prep_w<<<256, 256>>>(W0, w0p, 4096);
    prep_w<<<512, 256>>>(W1, w1p, 8192);
    prep_w<<<512, 256>>>(W2, w2p, 8192);

    dim3 grid(128), block(512);
    layer_mma<64,  true ><<<grid, block, SMEM_TOTAL>>>(input, input, w0p, b0, x1, out, 0);
    layer_mma<128, true ><<<grid, block, SMEM_TOTAL>>>(x1,    input, w1p, b1, x2, out, 128);
    layer_mma<128, false><<<grid, block, SMEM_TOTAL>>>(x2,    input, w2p, b2, nullptr, out, 256);
}